// round 7
// baseline (speedup 1.0000x reference)
#include <cuda_runtime.h>
#include <cstdint>

// Correlation: out[n,q,y,x] = (1/256) * sum_c d1[n,c,y,x] * d2[n,c,y+dy,x+dx]
// q = (dy+4)*9 + (dx+4), zero padding. N=8, C=256, H=96, W=160, 81 out channels.

#define HH 96
#define WW 160
#define CC 256
#define NN 8
#define TX 32
#define TY 4
#define CK 8
#define NTHREADS 144               // 4 x-octets * 9 dy * 4 rows
#define S1_ELEMS (CK*TY*TX)        // 1024 floats
#define S2_ROWS  (TY+8)            // 12
#define S2_COLS  44                // 40 data + 4 pad
#define S2_ELEMS (CK*S2_ROWS*S2_COLS)    // 4224 floats
#define BUF_ELEMS (S1_ELEMS + S2_ELEMS)  // 5248 floats per stage
#define SMEM_BYTES (2 * BUF_ELEMS * 4)   // 41984 per block

#define TASK_INVALID 0xFFFFFFFFu
// task = (src_elem_offset << 15) | (dst_byte_offset >> 2)
// src < 2^17 (max ~122880), dst/4 < 2^15 (max 5248) -- fits exactly.

__device__ __forceinline__ void cp_async16(uint32_t dst, const float* src) {
    asm volatile("cp.async.cg.shared.global [%0], [%1], 16;\n" :: "r"(dst), "l"(src));
}
__device__ __forceinline__ void cp_commit() {
    asm volatile("cp.async.commit_group;\n" ::: "memory");
}
__device__ __forceinline__ void cp_wait0() {
    asm volatile("cp.async.wait_group 0;\n" ::: "memory");
}
__device__ __forceinline__ void issue_task(uint32_t task, uint32_t smem_base,
                                           const float* gbase) {
    if (task != TASK_INVALID) {
        const uint32_t dst = (task & 0x7FFFu) << 2;
        const uint32_t src = task >> 15;
        cp_async16(smem_base + dst, gbase + src);
    }
}

__global__ __launch_bounds__(NTHREADS, 4)
void corr_kernel(const float* __restrict__ d1,
                 const float* __restrict__ d2,
                 float* __restrict__ out)
{
    extern __shared__ float smem[];
    const int tid = threadIdx.x;
    const int xo  = tid & 3;          // x-octet 0..3
    const int dyi = (tid >> 2) % 9;   // dy index 0..8
    const int ty  = tid / 36;         // row 0..3

    const int x0 = blockIdx.x * TX;
    const int y0 = blockIdx.y * TY;
    const int n  = blockIdx.z;

    const float* __restrict__ p1 = d1 + (size_t)n * CC * HH * WW;
    const float* __restrict__ p2 = d2 + (size_t)n * CC * HH * WW;

    const uint32_t smem_u32 = (uint32_t)__cvta_generic_to_shared(smem);

    // ---- zero both s2 buffers once (halo OOB + pad cols stay zero) ----
    {
        float4 z = make_float4(0.f, 0.f, 0.f, 0.f);
        #pragma unroll
        for (int b = 0; b < 2; b++) {
            float4* s2v = reinterpret_cast<float4*>(smem + b * BUF_ELEMS + S1_ELEMS);
            for (int i = tid; i < S2_ELEMS / 4; i += NTHREADS) s2v[i] = z;
        }
    }

    // ---- precompute packed load tasks (1 reg per task) ----
    // s1: 256 float4 tasks -> 2 per thread
    uint32_t t1[2];
    #pragma unroll
    for (int i = 0; i < 2; i++) {
        const int idx = tid + i * NTHREADS;
        if (idx < S1_ELEMS / 4) {
            const int c    = idx >> 5;
            const int rem  = idx & 31;
            const int row  = rem >> 3;
            const int col4 = rem & 7;
            const uint32_t src = c * (HH * WW) + (y0 + row) * WW + x0 + col4 * 4;
            const uint32_t dst = ((c * TY + row) * TX + col4 * 4) * 4;
            t1[i] = (src << 15) | (dst >> 2);
        } else {
            t1[i] = TASK_INVALID;
        }
    }

    // s2: 960 float4 tasks -> up to 7 per thread
    uint32_t t2[7];
    #pragma unroll
    for (int i = 0; i < 7; i++) {
        const int idx = tid + i * NTHREADS;
        bool v = (idx < CK * S2_ROWS * 10);
        int c = 0, row = 0, grp = 0;
        if (v) {
            c   = idx / (S2_ROWS * 10);
            int rem = idx - c * (S2_ROWS * 10);
            row = rem / 10;
            grp = rem - row * 10;
        }
        const int gy  = y0 + row - 4;
        const int gx0 = x0 + grp * 4 - 4;
        v = v && ((unsigned)gy < (unsigned)HH) && (gx0 >= 0) && (gx0 + 3 < WW);
        if (v) {
            const uint32_t src = c * (HH * WW) + gy * WW + gx0;
            const uint32_t dst = (S1_ELEMS + (c * S2_ROWS + row) * S2_COLS + grp * 4) * 4;
            t2[i] = (src << 15) | (dst >> 2);
        } else {
            t2[i] = TASK_INVALID;
        }
    }

    float acc[9][8];
    #pragma unroll
    for (int i = 0; i < 9; i++)
        #pragma unroll
        for (int j = 0; j < 8; j++) acc[i][j] = 0.0f;

    // zero-init must complete block-wide before prologue cp.async
    __syncthreads();

    // ---- prologue: chunk 0 into stage 0 ----
    #pragma unroll
    for (int i = 0; i < 2; i++) issue_task(t1[i], smem_u32, p1);
    #pragma unroll
    for (int i = 0; i < 7; i++) issue_task(t2[i], smem_u32, p2);
    cp_commit();

    const int NCHUNK = CC / CK;   // 32
    #pragma unroll 1
    for (int ci = 0; ci < NCHUNK; ci++) {
        cp_wait0();
        __syncthreads();

        if (ci + 1 < NCHUNK) {
            const uint32_t coff = (uint32_t)(ci + 1) * CK * (HH * WW);
            const uint32_t sb = smem_u32 + ((ci + 1) & 1) * (BUF_ELEMS * 4);
            #pragma unroll
            for (int i = 0; i < 2; i++) issue_task(t1[i], sb, p1 + coff);
            #pragma unroll
            for (int i = 0; i < 7; i++) issue_task(t2[i], sb, p2 + coff);
        }
        cp_commit();

        const float* __restrict__ s1 = smem + (ci & 1) * BUF_ELEMS;
        const float* __restrict__ s2 = s1 + S1_ELEMS;

        #pragma unroll
        for (int c = 0; c < CK; c++) {
            const float4* ap = reinterpret_cast<const float4*>(
                s1 + (c * TY + ty) * TX + xo * 8);
            const float4 a0 = ap[0];
            const float4 a1 = ap[1];
            const float4* wp = reinterpret_cast<const float4*>(
                s2 + (c * S2_ROWS + ty + dyi) * S2_COLS + xo * 8);
            const float4 w0 = wp[0];
            const float4 w1 = wp[1];
            const float4 w2 = wp[2];
            const float4 w3 = wp[3];

            float a[8], w[16];
            a[0]=a0.x; a[1]=a0.y; a[2]=a0.z; a[3]=a0.w;
            a[4]=a1.x; a[5]=a1.y; a[6]=a1.z; a[7]=a1.w;
            w[0]=w0.x;  w[1]=w0.y;  w[2]=w0.z;  w[3]=w0.w;
            w[4]=w1.x;  w[5]=w1.y;  w[6]=w1.z;  w[7]=w1.w;
            w[8]=w2.x;  w[9]=w2.y;  w[10]=w2.z; w[11]=w2.w;
            w[12]=w3.x; w[13]=w3.y; w[14]=w3.z; w[15]=w3.w;

            #pragma unroll
            for (int dxi = 0; dxi < 9; dxi++)
                #pragma unroll
                for (int p = 0; p < 8; p++)
                    acc[dxi][p] = fmaf(a[p], w[p + dxi], acc[dxi][p]);
        }
    }

    // ---- epilogue: 9 dx * 2 float4 stores ----
    const float scale = 1.0f / 256.0f;
    const int y  = y0 + ty;
    const int xb = x0 + xo * 8;
    #pragma unroll
    for (int dxi = 0; dxi < 9; dxi++) {
        const int q = dyi * 9 + dxi;
        float* op = out + (((size_t)n * 81 + q) * HH + y) * WW + xb;
        float4 o0, o1;
        o0.x = acc[dxi][0] * scale; o0.y = acc[dxi][1] * scale;
        o0.z = acc[dxi][2] * scale; o0.w = acc[dxi][3] * scale;
        o1.x = acc[dxi][4] * scale; o1.y = acc[dxi][5] * scale;
        o1.z = acc[dxi][6] * scale; o1.w = acc[dxi][7] * scale;
        reinterpret_cast<float4*>(op)[0] = o0;
        reinterpret_cast<float4*>(op)[1] = o1;
    }
}

extern "C" void kernel_launch(void* const* d_in, const int* in_sizes, int n_in,
                              void* d_out, int out_size)
{
    const float* d1 = (const float*)d_in[0];
    const float* d2 = (const float*)d_in[1];
    float* out = (float*)d_out;

    cudaFuncSetAttribute(corr_kernel,
                         cudaFuncAttributeMaxDynamicSharedMemorySize, SMEM_BYTES);

    dim3 grid(WW / TX, HH / TY, NN);   // (5, 24, 8)
    corr_kernel<<<grid, NTHREADS, SMEM_BYTES>>>(d1, d2, out);
}

// round 8
// speedup vs baseline: 1.4338x; 1.4338x over previous
#include <cuda_runtime.h>
#include <cstdint>

// Correlation: out[n,q,y,x] = (1/256) * sum_c d1[n,c,y,x] * d2[n,c,y+dy,x+dx]
// q = (dy+4)*9 + (dx+4), zero padding. N=8, C=256, H=96, W=160, 81 out channels.

#define HH 96
#define WW 160
#define CC 256
#define NN 8
#define TX 32
#define TY 4
#define CK 8
#define NTHREADS 144               // 4 x-octets * 9 dy * 4 rows
#define S1_ELEMS (CK*TY*TX)        // 1024 floats
#define S2_ROWS  (TY+8)            // 12
#define S2_COLS  44                // 40 data + 4 pad
#define S2_ELEMS (CK*S2_ROWS*S2_COLS)    // 4224 floats
#define BUF_ELEMS (S1_ELEMS + S2_ELEMS)  // 5248 floats per stage
#define NSTAGE 3
#define SMEM_BYTES (NSTAGE * BUF_ELEMS * 4)   // 62976 per block

#define TASK_INVALID 0xFFFFFFFFu
// task = (src_elem_offset << 15) | (dst_byte_offset >> 2)

__device__ __forceinline__ void cp_async16(uint32_t dst, const float* src) {
    asm volatile("cp.async.cg.shared.global [%0], [%1], 16;\n" :: "r"(dst), "l"(src));
}
__device__ __forceinline__ void cp_commit() {
    asm volatile("cp.async.commit_group;\n" ::: "memory");
}
__device__ __forceinline__ void cp_wait1() {
    asm volatile("cp.async.wait_group 1;\n" ::: "memory");
}
__device__ __forceinline__ void issue_task(uint32_t task, uint32_t smem_base,
                                           const float* gbase) {
    if (task != TASK_INVALID) {
        const uint32_t dst = (task & 0x7FFFu) << 2;
        const uint32_t src = task >> 15;
        cp_async16(smem_base + dst, gbase + src);
    }
}

__global__ __launch_bounds__(NTHREADS, 3)
void corr_kernel(const float* __restrict__ d1,
                 const float* __restrict__ d2,
                 float* __restrict__ out)
{
    extern __shared__ float smem[];
    const int tid = threadIdx.x;
    const int xo  = tid & 3;          // x-octet 0..3
    const int dyi = (tid >> 2) % 9;   // dy index 0..8
    const int ty  = tid / 36;         // row 0..3

    const int x0 = blockIdx.x * TX;
    const int y0 = blockIdx.y * TY;
    const int n  = blockIdx.z;

    const float* __restrict__ p1 = d1 + (size_t)n * CC * HH * WW;
    const float* __restrict__ p2 = d2 + (size_t)n * CC * HH * WW;

    const uint32_t smem_u32 = (uint32_t)__cvta_generic_to_shared(smem);

    // ---- zero all s2 buffers once (halo OOB + pad cols stay zero) ----
    {
        float4 z = make_float4(0.f, 0.f, 0.f, 0.f);
        #pragma unroll
        for (int b = 0; b < NSTAGE; b++) {
            float4* s2v = reinterpret_cast<float4*>(smem + b * BUF_ELEMS + S1_ELEMS);
            for (int i = tid; i < S2_ELEMS / 4; i += NTHREADS) s2v[i] = z;
        }
    }

    // ---- precompute packed load tasks (1 reg each) ----
    uint32_t t1[2];
    #pragma unroll
    for (int i = 0; i < 2; i++) {
        const int idx = tid + i * NTHREADS;
        if (idx < S1_ELEMS / 4) {
            const int c    = idx >> 5;
            const int rem  = idx & 31;
            const int row  = rem >> 3;
            const int col4 = rem & 7;
            const uint32_t src = c * (HH * WW) + (y0 + row) * WW + x0 + col4 * 4;
            const uint32_t dst = ((c * TY + row) * TX + col4 * 4) * 4;
            t1[i] = (src << 15) | (dst >> 2);
        } else t1[i] = TASK_INVALID;
    }

    uint32_t t2[7];
    #pragma unroll
    for (int i = 0; i < 7; i++) {
        const int idx = tid + i * NTHREADS;
        bool v = (idx < CK * S2_ROWS * 10);
        int c = 0, row = 0, grp = 0;
        if (v) {
            c   = idx / (S2_ROWS * 10);
            int rem = idx - c * (S2_ROWS * 10);
            row = rem / 10;
            grp = rem - row * 10;
        }
        const int gy  = y0 + row - 4;
        const int gx0 = x0 + grp * 4 - 4;
        v = v && ((unsigned)gy < (unsigned)HH) && (gx0 >= 0) && (gx0 + 3 < WW);
        if (v) {
            const uint32_t src = c * (HH * WW) + gy * WW + gx0;
            const uint32_t dst = (S1_ELEMS + (c * S2_ROWS + row) * S2_COLS + grp * 4) * 4;
            t2[i] = (src << 15) | (dst >> 2);
        } else t2[i] = TASK_INVALID;
    }

    float acc[9][8];
    #pragma unroll
    for (int i = 0; i < 9; i++)
        #pragma unroll
        for (int j = 0; j < 8; j++) acc[i][j] = 0.0f;

    // zero-init must complete block-wide before prologue cp.async
    __syncthreads();

    // ---- prologue: issue chunks 0 and 1 (stages 0, 1) ----
    #pragma unroll
    for (int s = 0; s < 2; s++) {
        const uint32_t coff = (uint32_t)s * CK * (HH * WW);
        const uint32_t sb = smem_u32 + s * (BUF_ELEMS * 4);
        #pragma unroll
        for (int i = 0; i < 2; i++) issue_task(t1[i], sb, p1 + coff);
        #pragma unroll
        for (int i = 0; i < 7; i++) issue_task(t2[i], sb, p2 + coff);
        cp_commit();
    }

    const int NCHUNK = CC / CK;   // 32
    int stage = 0;                // stage of chunk ci
    int stage2 = 2;               // stage of chunk ci+2
    #pragma unroll 1
    for (int ci = 0; ci < NCHUNK; ci++) {
        cp_wait1();        // chunk ci's group (oldest) complete; ci+1 may fly
        __syncthreads();   // all threads done computing ci-1 (frees stage of ci+2)

        if (ci + 2 < NCHUNK) {
            const uint32_t coff = (uint32_t)(ci + 2) * CK * (HH * WW);
            const uint32_t sb = smem_u32 + stage2 * (BUF_ELEMS * 4);
            #pragma unroll
            for (int i = 0; i < 2; i++) issue_task(t1[i], sb, p1 + coff);
            #pragma unroll
            for (int i = 0; i < 7; i++) issue_task(t2[i], sb, p2 + coff);
        }
        cp_commit();       // keep group count aligned (possibly empty)

        const float* __restrict__ s1 = smem + stage * BUF_ELEMS;
        const float* __restrict__ s2 = s1 + S1_ELEMS;

        #pragma unroll
        for (int c = 0; c < CK; c++) {
            const float4* ap = reinterpret_cast<const float4*>(
                s1 + (c * TY + ty) * TX + xo * 8);
            const float4 a0 = ap[0];
            const float4 a1 = ap[1];
            const float4* wp = reinterpret_cast<const float4*>(
                s2 + (c * S2_ROWS + ty + dyi) * S2_COLS + xo * 8);
            const float4 w0 = wp[0];
            const float4 w1 = wp[1];
            const float4 w2 = wp[2];
            const float4 w3 = wp[3];

            float a[8], w[16];
            a[0]=a0.x; a[1]=a0.y; a[2]=a0.z; a[3]=a0.w;
            a[4]=a1.x; a[5]=a1.y; a[6]=a1.z; a[7]=a1.w;
            w[0]=w0.x;  w[1]=w0.y;  w[2]=w0.z;  w[3]=w0.w;
            w[4]=w1.x;  w[5]=w1.y;  w[6]=w1.z;  w[7]=w1.w;
            w[8]=w2.x;  w[9]=w2.y;  w[10]=w2.z; w[11]=w2.w;
            w[12]=w3.x; w[13]=w3.y; w[14]=w3.z; w[15]=w3.w;

            #pragma unroll
            for (int dxi = 0; dxi < 9; dxi++)
                #pragma unroll
                for (int p = 0; p < 8; p++)
                    acc[dxi][p] = fmaf(a[p], w[p + dxi], acc[dxi][p]);
        }

        stage  = (stage  == NSTAGE - 1) ? 0 : stage + 1;
        stage2 = (stage2 == NSTAGE - 1) ? 0 : stage2 + 1;
    }

    // ---- epilogue: 9 dx * 2 float4 stores ----
    const float scale = 1.0f / 256.0f;
    const int y  = y0 + ty;
    const int xb = x0 + xo * 8;
    #pragma unroll
    for (int dxi = 0; dxi < 9; dxi++) {
        const int q = dyi * 9 + dxi;
        float* op = out + (((size_t)n * 81 + q) * HH + y) * WW + xb;
        float4 o0, o1;
        o0.x = acc[dxi][0] * scale; o0.y = acc[dxi][1] * scale;
        o0.z = acc[dxi][2] * scale; o0.w = acc[dxi][3] * scale;
        o1.x = acc[dxi][4] * scale; o1.y = acc[dxi][5] * scale;
        o1.z = acc[dxi][6] * scale; o1.w = acc[dxi][7] * scale;
        reinterpret_cast<float4*>(op)[0] = o0;
        reinterpret_cast<float4*>(op)[1] = o1;
    }
}

extern "C" void kernel_launch(void* const* d_in, const int* in_sizes, int n_in,
                              void* d_out, int out_size)
{
    const float* d1 = (const float*)d_in[0];
    const float* d2 = (const float*)d_in[1];
    float* out = (float*)d_out;

    cudaFuncSetAttribute(corr_kernel,
                         cudaFuncAttributeMaxDynamicSharedMemorySize, SMEM_BYTES);

    dim3 grid(WW / TX, HH / TY, NN);   // (5, 24, 8)
    corr_kernel<<<grid, NTHREADS, SMEM_BYTES>>>(d1, d2, out);
}